// round 2
// baseline (speedup 1.0000x reference)
#include <cuda_runtime.h>
#include <cuda_bf16.h>
#include <cstdint>

// Problem constants: x(4,256,64,64), p_w(18,256,3,3), p_b(18), conv_w(256,256,3,3)
// out(4,256,64,64). K=3, stride=1, pad=1. Hp=Wp=66.

#define NB   4
#define NC   256
#define NH   64
#define NW   64
#define NCO  256
#define NKK  9
#define KTOT 2304   // 256*9

// Scratch (device globals; allocation-free per harness rules)
__device__ float g_off[NB * 18 * NH * NW];                 // predicted offsets (B,18,H,W)
__device__ __align__(16) float g_wt[KTOT * NCO];           // conv_w transposed to [k][o]

// ---------------------------------------------------------------------------
// Kernel 0: transpose conv_w (O,C,3,3)=[o][k] -> g_wt[k][o]
// ---------------------------------------------------------------------------
__global__ void k_transpose(const float* __restrict__ w) {
    int e = blockIdx.x * 256 + threadIdx.x;   // 589824 total, grid exact
    int o = e / KTOT;
    int k = e - o * KTOT;
    g_wt[k * NCO + o] = w[e];
}

// ---------------------------------------------------------------------------
// Kernel 1: offset conv  (B,18,H,W) = conv3x3(x, p_w, pad=1) + p_b
// Block = one output row (b,h): 64 pixels. 256 threads = 4 K-splits x 64 pix.
// ---------------------------------------------------------------------------
__global__ void __launch_bounds__(256) k_offset(const float* __restrict__ x,
                                                const float* __restrict__ pw,
                                                const float* __restrict__ pb) {
    __shared__ __align__(16) float patch[4][3][68];   // 4 channel-groups, 3 rows, padded width
    __shared__ __align__(16) float ws[4][9][20];      // [grp][tap][oc padded 18->20]
    __shared__ float red[4][64][18];

    int b = blockIdx.x >> 6;
    int h = blockIdx.x & 63;
    int tid = threadIdx.x;
    int g   = tid >> 6;       // channel-group 0..3
    int pix = tid & 63;       // output w

    float acc[20];
#pragma unroll
    for (int i = 0; i < 20; i++) acc[i] = 0.f;

    const float* xb = x + ((size_t)b << 20);   // b*256*4096

    for (int cc = 0; cc < 64; cc++) {
        // load 4 channel patches (rows h-1..h+1, w -1..64)
        for (int l = tid; l < 4 * 3 * 66; l += 256) {
            int gg  = l / 198;
            int rem = l - gg * 198;
            int r   = rem / 66;
            int wc  = rem - r * 66;
            int y   = h + r - 1;
            int xw  = wc - 1;
            float v = 0.f;
            if (y >= 0 && y < NH && xw >= 0 && xw < NW)
                v = xb[((gg * 64 + cc) << 12) + (y << 6) + xw];
            patch[gg][r][wc] = v;
        }
        // load weights for the 4 channels (oc padded with zeros to 20)
        for (int l = tid; l < 720; l += 256) {
            int gg  = l / 180;
            int rem = l - gg * 180;
            int n   = rem / 20;
            int oc  = rem - n * 20;
            float v = 0.f;
            if (oc < 18) v = pw[oc * KTOT + (gg * 64 + cc) * 9 + n];
            ws[gg][n][oc] = v;
        }
        __syncthreads();

#pragma unroll
        for (int ky = 0; ky < 3; ky++) {
#pragma unroll
            for (int kx = 0; kx < 3; kx++) {
                float s = patch[g][ky][pix + kx];
                int n = ky * 3 + kx;
#pragma unroll
                for (int q = 0; q < 5; q++) {
                    float4 w4 = *(const float4*)&ws[g][n][q * 4];
                    acc[q * 4 + 0] += w4.x * s;
                    acc[q * 4 + 1] += w4.y * s;
                    acc[q * 4 + 2] += w4.z * s;
                    acc[q * 4 + 3] += w4.w * s;
                }
            }
        }
        __syncthreads();
    }

#pragma unroll
    for (int i = 0; i < 18; i++) red[g][pix][i] = acc[i];
    __syncthreads();

    for (int e = tid; e < 64 * 18; e += 256) {
        int p2 = e / 18;
        int oc = e - p2 * 18;
        float v = red[0][p2][oc] + red[1][p2][oc] + red[2][p2][oc] + red[3][p2][oc] + pb[oc];
        g_off[((b * 18 + oc) << 12) + (h << 6) + p2] = v;
    }
}

// ---------------------------------------------------------------------------
// Kernel 2: fused bilinear sampling + implicit GEMM (M=256 oc, K=2304, 64 pix/block)
// ---------------------------------------------------------------------------
__device__ __forceinline__ void cp16(void* smem_dst, const void* gsrc) {
    uint32_t s = (uint32_t)__cvta_generic_to_shared(smem_dst);
    asm volatile("cp.async.cg.shared.global [%0], [%1], 16;" ::"r"(s), "l"(gsrc));
}
__device__ __forceinline__ void cp_commit() { asm volatile("cp.async.commit_group;"); }
__device__ __forceinline__ void cp_wait1()  { asm volatile("cp.async.wait_group 1;"); }
__device__ __forceinline__ void cp_wait0()  { asm volatile("cp.async.wait_group 0;"); }

__device__ __forceinline__ void produce_S(float* Sd, const float* __restrict__ xb,
                                          const int* idxs, const float* wgts,
                                          int c0, int tid) {
#pragma unroll
    for (int i = 0; i < 9; i++) {
        int e2  = tid + (i << 8);      // 0..2303
        int k   = e2 >> 6;             // 0..35
        int pix = e2 & 63;
        int ci  = k / 9;
        int n   = k - ci * 9;
        const float* xp = xb + ((c0 + ci) << 12);
        int te = (pix * 9 + n) << 2;
        int4   id = *(const int4*)(idxs + te);
        float4 wg = *(const float4*)(wgts + te);
        Sd[(k << 6) + pix] = wg.x * xp[id.x] + wg.y * xp[id.y] +
                             wg.z * xp[id.z] + wg.w * xp[id.w];
    }
}

__global__ void __launch_bounds__(256) k_main(const float* __restrict__ x,
                                              float* __restrict__ out) {
    extern __shared__ __align__(16) char smem_raw[];
    float* Ws   = (float*)smem_raw;          // [2][36][256]  73728 B
    float* Ss   = Ws + 2 * 36 * 256;         // [2][36][64]   18432 B
    int*   idxs = (int*)(Ss + 2 * 36 * 64);  // [576][4]       9216 B
    float* wgts = (float*)(idxs + 576 * 4);  // [576][4]       9216 B

    int b   = blockIdx.x >> 6;
    int h   = blockIdx.x & 63;
    int tid = threadIdx.x;
    const float* xb = x + ((size_t)b << 20);

    // ---- per-block bilinear tables: 64 pixels x 9 taps, 4 corners each ----
    for (int e = tid; e < 576; e += 256) {
        int pix = e / 9;
        int n   = e - pix * 9;
        int gbase = ((b * 18 + n) << 12) + (h << 6) + pix;
        float offy = g_off[gbase];
        float offx = g_off[gbase + (9 << 12)];
        int ky = n / 3;
        int kx = n - ky * 3;
        float py = (float)(h + ky) + offy;     // padded-image coords
        float px = (float)(pix + kx) + offx;
        float fy = floorf(py), fx = floorf(px);
        float qlty = fminf(fmaxf(fy, 0.f), 65.f);
        float qrby = fminf(fmaxf(fy + 1.f, 0.f), 65.f);
        float qltx = fminf(fmaxf(fx, 0.f), 65.f);
        float qrbx = fminf(fmaxf(fx + 1.f, 0.f), 65.f);
        float pyc = fminf(fmaxf(py, 0.f), 65.f);
        float pxc = fminf(fmaxf(px, 0.f), 65.f);
        float dly = 1.f + qlty - pyc, dry = 1.f - qrby + pyc;
        float dlx = 1.f + qltx - pxc, drx = 1.f - qrbx + pxc;
        int ily = (int)qlty, iry = (int)qrby, ilx = (int)qltx, irx = (int)qrbx;
        bool vly = (ily >= 1) && (ily <= 64), vry = (iry >= 1) && (iry <= 64);
        bool vlx = (ilx >= 1) && (ilx <= 64), vrx = (irx >= 1) && (irx <= 64);
        int bly = (ily - 1) << 6, bry = (iry - 1) << 6;
        int   i0 = (vly && vlx) ? bly + ilx - 1 : 0;
        float w0 = (vly && vlx) ? dly * dlx : 0.f;
        int   i1 = (vry && vrx) ? bry + irx - 1 : 0;
        float w1 = (vry && vrx) ? dry * drx : 0.f;
        int   i2 = (vly && vrx) ? bly + irx - 1 : 0;
        float w2 = (vly && vrx) ? dly * drx : 0.f;
        int   i3 = (vry && vlx) ? bry + ilx - 1 : 0;
        float w3 = (vry && vlx) ? dry * dlx : 0.f;
        *(int4*)(idxs + e * 4)   = make_int4(i0, i1, i2, i3);
        *(float4*)(wgts + e * 4) = make_float4(w0, w1, w2, w3);
    }
    __syncthreads();

    // ---- prologue: S chunk0 + async W chunk0 ----
    produce_S(Ss, xb, idxs, wgts, 0, tid);
    {
        const float4* src = (const float4*)(g_wt);
#pragma unroll
        for (int i = 0; i < 9; i++) {
            int e2 = tid + (i << 8);
            cp16((float4*)Ws + e2, src + e2);
        }
        cp_commit();
    }

    float acc[8][8];
#pragma unroll
    for (int o = 0; o < 8; o++)
#pragma unroll
        for (int p = 0; p < 8; p++) acc[o][p] = 0.f;

    int og = tid >> 3;   // 0..31 -> 8 output channels each
    int pg = tid & 7;    // 0..7  -> 8 pixels each

    for (int ch = 0; ch < 64; ch++) {
        int cur = ch & 1;
        float* Wc = Ws + cur * 9216;
        float* Sc = Ss + cur * 2304;
        float* Wn = Ws + (cur ^ 1) * 9216;
        float* Sn = Ss + (cur ^ 1) * 2304;

        __syncthreads();   // everyone done reading the 'next' buffers from ch-1
        if (ch + 1 < 64) {
            // FIX: chunk stride is 36 k-rows * 256 oc = 9216 floats (was 9*256)
            const float4* src = (const float4*)(g_wt + (size_t)(ch + 1) * 36 * 256);
#pragma unroll
            for (int i = 0; i < 9; i++) {
                int e2 = tid + (i << 8);
                cp16((float4*)Wn + e2, src + e2);
            }
            cp_commit();
            cp_wait1();    // current chunk's W has landed
        } else {
            cp_wait0();
        }
        __syncthreads();   // all threads' W(cur) visible; S(cur) produced last iter

        // ---- GEMM: 36 k-steps, 8x8 register tile ----
#pragma unroll 4
        for (int k = 0; k < 36; k++) {
            float4 wA = *(const float4*)(Wc + (k << 8) + og * 8);
            float4 wB = *(const float4*)(Wc + (k << 8) + og * 8 + 4);
            float4 sA = *(const float4*)(Sc + (k << 6) + pg * 8);
            float4 sB = *(const float4*)(Sc + (k << 6) + pg * 8 + 4);
            float wv[8] = {wA.x, wA.y, wA.z, wA.w, wB.x, wB.y, wB.z, wB.w};
            float sv[8] = {sA.x, sA.y, sA.z, sA.w, sB.x, sB.y, sB.z, sB.w};
#pragma unroll
            for (int o = 0; o < 8; o++)
#pragma unroll
                for (int p = 0; p < 8; p++) acc[o][p] += wv[o] * sv[p];
        }

        // ---- produce next S behind the compute ----
        if (ch + 1 < 64)
            produce_S(Sn, xb, idxs, wgts, (ch + 1) * 4, tid);
    }

    // ---- store: out(b, oc, h, w) ----
    float* ob = out + ((size_t)b << 20) + (h << 6) + (pg << 3);
#pragma unroll
    for (int o = 0; o < 8; o++) {
        float* p = ob + ((og * 8 + o) << 12);
        *(float4*)p       = make_float4(acc[o][0], acc[o][1], acc[o][2], acc[o][3]);
        *(float4*)(p + 4) = make_float4(acc[o][4], acc[o][5], acc[o][6], acc[o][7]);
    }
}

// ---------------------------------------------------------------------------
extern "C" void kernel_launch(void* const* d_in, const int* in_sizes, int n_in,
                              void* d_out, int out_size) {
    const float* x  = (const float*)d_in[0];   // (4,256,64,64)
    const float* pw = (const float*)d_in[1];   // (18,256,3,3)
    const float* pb = (const float*)d_in[2];   // (18,)
    const float* cw = (const float*)d_in[3];   // (256,256,3,3)
    float* out = (float*)d_out;

    cudaFuncSetAttribute(k_main, cudaFuncAttributeMaxDynamicSharedMemorySize, 110592);

    k_transpose<<<KTOT * NCO / 256, 256>>>(cw);
    k_offset<<<NB * NH, 256>>>(x, pw, pb);
    k_main<<<NB * NH, 256, 110592>>>(x, out);
}